// round 9
// baseline (speedup 1.0000x reference)
#include <cuda_runtime.h>
#include <mma.h>

using namespace nvcuda;

#define IN_F  4096
#define OUT_F 4096
#define MROWS 4096
#define KDIM  4096

#define BM 128
#define BN 128
#define BK 16
#define LDT 24                  // padded smem row (floats)
#define TILE_F (BM * LDT)
#define STAGE_F (3 * TILE_F)    // Ah, Al, W per stage
#define STAGES 3
#define KT (KDIM / BK)
#define SMEM_BYTES (STAGES * STAGE_F * 4)   // 110592 B

// Scratch (allocation-free rule: device globals)
__device__ float g_Xh[(size_t)MROWS * IN_F];  // tf32 hi part of x
__device__ float g_Xl[(size_t)MROWS * IN_F];  // tf32 lo part of x
__device__ float g_W [(size_t)OUT_F * IN_F];  // W = (q-8)*s + residual, tf32-rounded

__device__ __forceinline__ float tf32r(float x) {
    float r;
    asm("cvt.rna.tf32.f32 %0, %1;" : "=f"(r) : "f"(x));
    return r;
}

__device__ __forceinline__ void cp16(float* dst, const float* src) {
    unsigned sd = (unsigned)__cvta_generic_to_shared(dst);
    asm volatile("cp.async.cg.shared.global [%0], [%1], 16;" :: "r"(sd), "l"(src));
}

// ---------------- kernel 0: split x into tf32 hi/lo (exact to 2^-22) ----------------
__global__ void split_x_kernel(const float* __restrict__ x, int n4) {
    int i = blockIdx.x * blockDim.x + threadIdx.x;
    if (i < n4) {
        float4 v = reinterpret_cast<const float4*>(x)[i];
        float4 h, l;
        h.x = tf32r(v.x); l.x = tf32r(v.x - h.x);
        h.y = tf32r(v.y); l.y = tf32r(v.y - h.y);
        h.z = tf32r(v.z); l.z = tf32r(v.z - h.z);
        h.w = tf32r(v.w); l.w = tf32r(v.w - h.w);
        reinterpret_cast<float4*>(g_Xh)[i] = h;
        reinterpret_cast<float4*>(g_Xl)[i] = l;
    }
}

// ---------------- kernel 1: dequant int4 -> fp32 W = (q-8)*s ----------------
__global__ void dequant_kernel(const int* __restrict__ packed,
                               const float* __restrict__ scales) {
    int i = blockIdx.x * blockDim.x + threadIdx.x;   // over OUT_F * IN_F/2 words
    if (i < OUT_F * (IN_F / 2)) {
        int row = i >> 11;                            // IN_F/2 = 2048
        int p = packed[i];
        float s = scales[row];
        float2 w;
        w.x = (float)((p & 15) - 8) * s;              // even col
        w.y = (float)(((p >> 4) & 15) - 8) * s;       // odd col
        reinterpret_cast<float2*>(g_W)[i] = w;
    }
}

// ---------------- kernel 2: CSR scatter-add residual (fp32 vals!) ----------------
// row r owns j in [ptr[r], ptr[r+1]) ∩ [0, nnz); duplicates sum -> atomicAdd.
__global__ void scatter_kernel(const float* __restrict__ vals,
                               const int* __restrict__ idxs,
                               const int* __restrict__ ptr,
                               int nnz) {
    int r = blockIdx.x;
    int s = ptr[r], e = ptr[r + 1];
    if (e > nnz) e = nnz;
    if (s > nnz) s = nnz;
    if (s < 0) s = 0;
    for (int j = s + threadIdx.x; j < e; j += blockDim.x) {
        int c = idxs[j];
        if ((unsigned)c < (unsigned)IN_F) {
            atomicAdd(&g_W[(size_t)r * IN_F + c], vals[j]);
        }
    }
}

// ---------------- kernel 3: tf32-round W in place ----------------
__global__ void round_w_kernel(int n4) {
    int i = blockIdx.x * blockDim.x + threadIdx.x;
    if (i < n4) {
        float4 v = reinterpret_cast<float4*>(g_W)[i];
        v.x = tf32r(v.x); v.y = tf32r(v.y); v.z = tf32r(v.z); v.w = tf32r(v.w);
        reinterpret_cast<float4*>(g_W)[i] = v;
    }
}

// ---------------- kernel 4: GEMM  out[m][n] = sum_k (xh+xl)[m][k] * W[n][k] ----------
__global__ __launch_bounds__(256, 2) void gemm_kernel(float* __restrict__ out) {
    extern __shared__ float sm[];

    const int tid  = threadIdx.x;
    const int bm0  = blockIdx.y * BM;
    const int bn0  = blockIdx.x * BN;
    const int warp = tid >> 5;
    const int lane = tid & 31;
    const int wm   = warp & 3;   // 0..3 -> 32-row band
    const int wn   = warp >> 2;  // 0..1 -> 64-col band

    wmma::fragment<wmma::accumulator, 16, 16, 8, float> C[2][4];
    #pragma unroll
    for (int i = 0; i < 2; i++)
        #pragma unroll
        for (int j = 0; j < 4; j++)
            wmma::fill_fragment(C[i][j], 0.0f);

    auto load_stage = [&](int kt, int s) {
        float* base = sm + s * STAGE_F;
        #pragma unroll
        for (int t = 0; t < 6; t++) {
            int c = t * 256 + tid;            // 0..1535
            int tile = c >> 9;                // 0=Ah 1=Al 2=W
            int cc   = c & 511;
            int row  = cc >> 2;
            int kc   = (cc & 3) * 4;
            const float* src;
            if (tile == 0)      src = g_Xh + (size_t)(bm0 + row) * KDIM + kt * BK + kc;
            else if (tile == 1) src = g_Xl + (size_t)(bm0 + row) * KDIM + kt * BK + kc;
            else                src = g_W  + (size_t)(bn0 + row) * KDIM + kt * BK + kc;
            cp16(base + tile * TILE_F + row * LDT + kc, src);
        }
        asm volatile("cp.async.commit_group;" ::: "memory");
    };

    load_stage(0, 0);
    load_stage(1, 1);

    for (int kt = 0; kt < KT; ++kt) {
        if (kt < KT - 1) asm volatile("cp.async.wait_group 1;" ::: "memory");
        else             asm volatile("cp.async.wait_group 0;" ::: "memory");
        __syncthreads();

        if (kt + 2 < KT) load_stage(kt + 2, (kt + 2) % STAGES);

        const float* Ah = sm + (kt % STAGES) * STAGE_F;
        const float* Al = Ah + TILE_F;
        const float* Bt = Ah + 2 * TILE_F;

        #pragma unroll
        for (int ks = 0; ks < 2; ++ks) {
            wmma::fragment<wmma::matrix_a, 16, 16, 8, wmma::precision::tf32, wmma::row_major> ah[2], al[2];
            wmma::fragment<wmma::matrix_b, 16, 16, 8, wmma::precision::tf32, wmma::col_major> bf[4];
            #pragma unroll
            for (int i = 0; i < 2; i++) {
                wmma::load_matrix_sync(ah[i], Ah + (wm * 32 + i * 16) * LDT + ks * 8, LDT);
                wmma::load_matrix_sync(al[i], Al + (wm * 32 + i * 16) * LDT + ks * 8, LDT);
            }
            #pragma unroll
            for (int j = 0; j < 4; j++)
                wmma::load_matrix_sync(bf[j], Bt + (wn * 64 + j * 16) * LDT + ks * 8, LDT);
            #pragma unroll
            for (int i = 0; i < 2; i++)
                #pragma unroll
                for (int j = 0; j < 4; j++) {
                    wmma::mma_sync(C[i][j], ah[i], bf[j], C[i][j]);
                    wmma::mma_sync(C[i][j], al[i], bf[j], C[i][j]);
                }
        }
        __syncthreads();
    }

    // ---- epilogue: stage accumulators through smem, vectorized store ----
    float* ws = sm + warp * (32 * 64);
    #pragma unroll
    for (int i = 0; i < 2; i++)
        #pragma unroll
        for (int j = 0; j < 4; j++)
            wmma::store_matrix_sync(ws + i * 16 * 64 + j * 16, C[i][j], 64, wmma::mem_row_major);
    __syncwarp();

    const int m_base = bm0 + wm * 32;
    const int n_base = bn0 + wn * 64;
    #pragma unroll
    for (int it = 0; it < 16; it++) {
        int e  = it * 32 + lane;
        int r  = e >> 4;
        int c4 = (e & 15) * 4;
        float4 v = *reinterpret_cast<float4*>(ws + r * 64 + c4);
        *reinterpret_cast<float4*>(out + (size_t)(m_base + r) * OUT_F + n_base + c4) = v;
    }
}

extern "C" void kernel_launch(void* const* d_in, const int* in_sizes, int n_in,
                              void* d_out, int out_size) {
    // Size-based binding; the two nnz-sized inputs keep metadata order:
    // ortho_vals first (stored FLOAT32 — established by rounds 4–8 analysis),
    // ortho_indices (int32) second.
    const float* x      = nullptr;
    const int*   packed = nullptr;
    const float* scales = nullptr;
    const float* vals   = nullptr;
    const int*   idxs   = nullptr;
    const int*   ptr    = nullptr;
    int nnz = 0;
    for (int i = 0; i < n_in; i++) {
        int sz = in_sizes[i];
        if (sz == MROWS * IN_F)            x      = (const float*)d_in[i];
        else if (sz == OUT_F * (IN_F / 2)) packed = (const int*)d_in[i];
        else if (sz == OUT_F)              scales = (const float*)d_in[i];
        else if (sz == OUT_F + 1)          ptr    = (const int*)d_in[i];
        else {
            nnz = sz;
            if (!vals) vals = (const float*)d_in[i];
            else       idxs = (const int*)d_in[i];
        }
    }
    float* out = (float*)d_out;

    int nx4 = (MROWS * IN_F) / 4;
    split_x_kernel<<<(nx4 + 255) / 256, 256>>>(x, nx4);

    int nw = OUT_F * (IN_F / 2);
    dequant_kernel<<<(nw + 255) / 256, 256>>>(packed, scales);

    scatter_kernel<<<OUT_F, 128>>>(vals, idxs, ptr, nnz);

    int nw4 = (OUT_F * IN_F) / 4;
    round_w_kernel<<<(nw4 + 255) / 256, 256>>>(nw4);

    cudaFuncSetAttribute(gemm_kernel, cudaFuncAttributeMaxDynamicSharedMemorySize, SMEM_BYTES);
    dim3 grid(OUT_F / BN, MROWS / BM);
    gemm_kernel<<<grid, 256, SMEM_BYTES>>>(out);
}

// round 12
// speedup vs baseline: 1.7381x; 1.7381x over previous
#include <cuda_runtime.h>
#include <mma.h>

using namespace nvcuda;

#define IN_F  4096
#define OUT_F 4096
#define MROWS 4096
#define KDIM  4096

#define BM 128
#define BN 128
#define BK 16
#define LDT 24                  // padded smem row (floats)
#define TILE_F (BM * LDT)       // 3072 floats
#define STAGE_F (2 * TILE_F)    // A, W per stage
#define STAGES 4
#define KT (KDIM / BK)          // 256
#define SMEM_BYTES (STAGES * STAGE_F * 4)   // 98304 B

// Scratch (allocation-free rule: device global)
__device__ float g_W[(size_t)OUT_F * IN_F];   // W = (q-8)*s + residual (fp32)

__device__ __forceinline__ float tf32r(float x) {
    float r;
    asm("cvt.rna.tf32.f32 %0, %1;" : "=f"(r) : "f"(x));
    return r;
}

__device__ __forceinline__ void cp16(float* dst, const float* src) {
    unsigned sd = (unsigned)__cvta_generic_to_shared(dst);
    asm volatile("cp.async.cg.shared.global [%0], [%1], 16;" :: "r"(sd), "l"(src));
}

// ---------------- kernel 0: dequant int4 -> fp32 W = (q-8)*s ----------------
__global__ void dequant_kernel(const int* __restrict__ packed,
                               const float* __restrict__ scales) {
    int i = blockIdx.x * blockDim.x + threadIdx.x;   // over OUT_F * IN_F/2 words
    if (i < OUT_F * (IN_F / 2)) {
        int row = i >> 11;                            // IN_F/2 = 2048
        int p = packed[i];
        float s = scales[row];
        float2 w;
        w.x = (float)((p & 15) - 8) * s;
        w.y = (float)(((p >> 4) & 15) - 8) * s;
        reinterpret_cast<float2*>(g_W)[i] = w;
    }
}

// ---------------- kernel 1: CSR scatter-add residual (fp32 vals) ----------------
__global__ void scatter_kernel(const float* __restrict__ vals,
                               const int* __restrict__ idxs,
                               const int* __restrict__ ptr,
                               int nnz) {
    int r = blockIdx.x;
    int s = ptr[r], e = ptr[r + 1];
    if (e > nnz) e = nnz;
    if (s > nnz) s = nnz;
    if (s < 0) s = 0;
    for (int j = s + threadIdx.x; j < e; j += blockDim.x) {
        int c = idxs[j];
        if ((unsigned)c < (unsigned)IN_F) {
            atomicAdd(&g_W[(size_t)r * IN_F + c], vals[j]);
        }
    }
}

// ---------------- kernel 2: single-pass tf32 GEMM, in-register RNA rounding ------
// out[m][n] = sum_k tf32(x[m][k]) * tf32(W[n][k]), fp32 accumulate.
__global__ __launch_bounds__(256, 2) void gemm_kernel(const float* __restrict__ x,
                                                      float* __restrict__ out) {
    extern __shared__ float sm[];

    const int tid  = threadIdx.x;
    const int bm0  = blockIdx.y * BM;
    const int bn0  = blockIdx.x * BN;
    const int warp = tid >> 5;
    const int lane = tid & 31;
    const int wm   = warp & 3;   // 0..3 -> 32-row band
    const int wn   = warp >> 2;  // 0..1 -> 64-col band

    wmma::fragment<wmma::accumulator, 16, 16, 8, float> C[2][4];
    #pragma unroll
    for (int i = 0; i < 2; i++)
        #pragma unroll
        for (int j = 0; j < 4; j++)
            wmma::fill_fragment(C[i][j], 0.0f);

    auto load_stage = [&](int kt, int s) {
        float* base = sm + s * STAGE_F;
        #pragma unroll
        for (int t = 0; t < 4; t++) {
            int c = t * 256 + tid;            // 0..1023
            int tile = c >> 9;                // 0=A 1=W
            int cc   = c & 511;
            int row  = cc >> 2;
            int kc   = (cc & 3) * 4;
            const float* src = (tile == 0)
                ? x   + (size_t)(bm0 + row) * KDIM + kt * BK + kc
                : g_W + (size_t)(bn0 + row) * KDIM + kt * BK + kc;
            cp16(base + tile * TILE_F + row * LDT + kc, src);
        }
        asm volatile("cp.async.commit_group;" ::: "memory");
    };

    load_stage(0, 0);
    load_stage(1, 1);
    load_stage(2, 2);

    for (int kt = 0; kt < KT; ++kt) {
        if (kt < KT - 2)      asm volatile("cp.async.wait_group 2;" ::: "memory");
        else if (kt == KT - 2) asm volatile("cp.async.wait_group 1;" ::: "memory");
        else                  asm volatile("cp.async.wait_group 0;" ::: "memory");
        __syncthreads();

        if (kt + 3 < KT) load_stage(kt + 3, (kt + 3) & 3);

        const float* At = sm + (kt & 3) * STAGE_F;
        const float* Bt = At + TILE_F;

        #pragma unroll
        for (int ks = 0; ks < 2; ++ks) {
            wmma::fragment<wmma::matrix_a, 16, 16, 8, wmma::precision::tf32, wmma::row_major> af[2];
            wmma::fragment<wmma::matrix_b, 16, 16, 8, wmma::precision::tf32, wmma::col_major> bf[4];
            #pragma unroll
            for (int i = 0; i < 2; i++) {
                wmma::load_matrix_sync(af[i], At + (wm * 32 + i * 16) * LDT + ks * 8, LDT);
                #pragma unroll
                for (int t = 0; t < af[i].num_elements; t++)
                    af[i].x[t] = tf32r(af[i].x[t]);
            }
            #pragma unroll
            for (int j = 0; j < 4; j++) {
                wmma::load_matrix_sync(bf[j], Bt + (wn * 64 + j * 16) * LDT + ks * 8, LDT);
                #pragma unroll
                for (int t = 0; t < bf[j].num_elements; t++)
                    bf[j].x[t] = tf32r(bf[j].x[t]);
            }
            #pragma unroll
            for (int i = 0; i < 2; i++)
                #pragma unroll
                for (int j = 0; j < 4; j++)
                    wmma::mma_sync(C[i][j], af[i], bf[j], C[i][j]);
        }
    }

    // ---- epilogue: stage accumulators through smem, vectorized store ----
    __syncthreads();
    float* ws = sm + warp * (32 * 64);
    #pragma unroll
    for (int i = 0; i < 2; i++)
        #pragma unroll
        for (int j = 0; j < 4; j++)
            wmma::store_matrix_sync(ws + i * 16 * 64 + j * 16, C[i][j], 64, wmma::mem_row_major);
    __syncwarp();

    const int m_base = bm0 + wm * 32;
    const int n_base = bn0 + wn * 64;
    #pragma unroll
    for (int it = 0; it < 16; it++) {
        int e  = it * 32 + lane;
        int r  = e >> 4;
        int c4 = (e & 15) * 4;
        float4 v = *reinterpret_cast<float4*>(ws + r * 64 + c4);
        *reinterpret_cast<float4*>(out + (size_t)(m_base + r) * OUT_F + n_base + c4) = v;
    }
}

extern "C" void kernel_launch(void* const* d_in, const int* in_sizes, int n_in,
                              void* d_out, int out_size) {
    // Size-based binding; the two nnz-sized inputs keep metadata order:
    // ortho_vals first (stored float32), ortho_indices (int32) second.
    const float* x      = nullptr;
    const int*   packed = nullptr;
    const float* scales = nullptr;
    const float* vals   = nullptr;
    const int*   idxs   = nullptr;
    const int*   ptr    = nullptr;
    int nnz = 0;
    for (int i = 0; i < n_in; i++) {
        int sz = in_sizes[i];
        if (sz == MROWS * IN_F)            x      = (const float*)d_in[i];
        else if (sz == OUT_F * (IN_F / 2)) packed = (const int*)d_in[i];
        else if (sz == OUT_F)              scales = (const float*)d_in[i];
        else if (sz == OUT_F + 1)          ptr    = (const int*)d_in[i];
        else {
            nnz = sz;
            if (!vals) vals = (const float*)d_in[i];
            else       idxs = (const int*)d_in[i];
        }
    }
    float* out = (float*)d_out;

    int nw = OUT_F * (IN_F / 2);
    dequant_kernel<<<(nw + 255) / 256, 256>>>(packed, scales);

    scatter_kernel<<<OUT_F, 128>>>(vals, idxs, ptr, nnz);

    cudaFuncSetAttribute(gemm_kernel, cudaFuncAttributeMaxDynamicSharedMemorySize, SMEM_BYTES);
    dim3 grid(OUT_F / BN, MROWS / BM);
    gemm_kernel<<<grid, 256, SMEM_BYTES>>>(x, out);
}

// round 14
// speedup vs baseline: 2.4277x; 1.3967x over previous
#include <cuda_runtime.h>
#include <cstdint>

#define IN_F  4096
#define OUT_F 4096
#define MROWS 4096
#define KDIM  4096

#define BM 128
#define BN 256
#define BK 16
#define STAGES 4
#define KT (KDIM / BK)              // 256
#define A_ST_F (BM * BK)            // 2048 floats / stage
#define B_ST_F (BN * BK)            // 4096 floats / stage
#define STAGE_F (A_ST_F + B_ST_F)   // 6144
#define SMEM_BYTES (STAGES * STAGE_F * 4)   // 98304

// Scratch (allocation-free rule: device globals). Both arrays hold tf32-RNA-
// rounded data in a K-PERMUTED layout: within every k8 group, element k sits
// at slot (k&3)*2 + (k>>2). This makes each mma.m16n8k8 fragment's two
// k-values (tig, tig+4) adjacent -> one LDS.64 per fragment.
__device__ float g_X[(size_t)MROWS * IN_F];
__device__ float g_W[(size_t)OUT_F * IN_F];

__device__ __forceinline__ float tf32r(float x) {
    float r;
    asm("cvt.rna.tf32.f32 %0, %1;" : "=f"(r) : "f"(x));
    return r;
}
__device__ __forceinline__ void cp16(float* dst, const float* src) {
    unsigned sd = (unsigned)__cvta_generic_to_shared(dst);
    asm volatile("cp.async.cg.shared.global [%0], [%1], 16;" :: "r"(sd), "l"(src));
}
__device__ __forceinline__ void mma_tf32(float c[4], float a0, float a1, float a2, float a3,
                                         float b0, float b1) {
    asm volatile(
        "mma.sync.aligned.m16n8k8.row.col.f32.tf32.tf32.f32 "
        "{%0,%1,%2,%3}, {%4,%5,%6,%7}, {%8,%9}, {%0,%1,%2,%3};"
        : "+f"(c[0]), "+f"(c[1]), "+f"(c[2]), "+f"(c[3])
        : "r"(__float_as_uint(a0)), "r"(__float_as_uint(a1)),
          "r"(__float_as_uint(a2)), "r"(__float_as_uint(a3)),
          "r"(__float_as_uint(b0)), "r"(__float_as_uint(b1)));
}

// ---------------- kernel 0: round x to tf32 + K-permute into g_X ----------------
// Thread i handles 8 consecutive k (one k8 group): j0..j7 -> (j0,j4,j1,j5),(j2,j6,j3,j7)
__global__ void permute_x_kernel(const float4* __restrict__ x4, int n8) {
    int i = blockIdx.x * blockDim.x + threadIdx.x;
    if (i < n8) {
        float4 a = x4[2 * i], b = x4[2 * i + 1];
        float4 o0 = make_float4(tf32r(a.x), tf32r(b.x), tf32r(a.y), tf32r(b.y));
        float4 o1 = make_float4(tf32r(a.z), tf32r(b.z), tf32r(a.w), tf32r(b.w));
        reinterpret_cast<float4*>(g_X)[2 * i]     = o0;
        reinterpret_cast<float4*>(g_X)[2 * i + 1] = o1;
    }
}

// ---------------- kernel 1: dequant int4 -> fp32 (q-8)*s, K-permuted ----------------
// Thread i handles 4 packed words = cols 8i..8i+7 (one k8 group) of row i>>9.
__global__ void dequant_kernel(const int4* __restrict__ packed4,
                               const float* __restrict__ scales, int n8) {
    int i = blockIdx.x * blockDim.x + threadIdx.x;
    if (i < n8) {
        int4 p = packed4[i];
        float s = scales[i >> 9];          // 512 groups of 8 cols per row
        float j0 = (float)((p.x & 15) - 8) * s, j1 = (float)(((p.x >> 4) & 15) - 8) * s;
        float j2 = (float)((p.y & 15) - 8) * s, j3 = (float)(((p.y >> 4) & 15) - 8) * s;
        float j4 = (float)((p.z & 15) - 8) * s, j5 = (float)(((p.z >> 4) & 15) - 8) * s;
        float j6 = (float)((p.w & 15) - 8) * s, j7 = (float)(((p.w >> 4) & 15) - 8) * s;
        reinterpret_cast<float4*>(g_W)[2 * i]     = make_float4(j0, j4, j1, j5);
        reinterpret_cast<float4*>(g_W)[2 * i + 1] = make_float4(j2, j6, j3, j7);
    }
}

// ---------------- kernel 2: CSR scatter-add residual (fp32 vals, permuted col) ------
__global__ void scatter_kernel(const float* __restrict__ vals,
                               const int* __restrict__ idxs,
                               const int* __restrict__ ptr,
                               int nnz) {
    int r = blockIdx.x;
    int s = ptr[r], e = ptr[r + 1];
    if (e > nnz) e = nnz;
    if (s > nnz) s = nnz;
    if (s < 0) s = 0;
    for (int j = s + threadIdx.x; j < e; j += blockDim.x) {
        int c = idxs[j];
        if ((unsigned)c < (unsigned)IN_F) {
            int pc = (c & ~7) | (((c & 3) << 1) | ((c >> 2) & 1));
            atomicAdd(&g_W[(size_t)r * IN_F + pc], vals[j]);
        }
    }
}

// ---------------- kernel 3: tf32-round W in place (post-scatter) ----------------
__global__ void round_w_kernel(int n4) {
    int i = blockIdx.x * blockDim.x + threadIdx.x;
    if (i < n4) {
        float4 v = reinterpret_cast<float4*>(g_W)[i];
        v.x = tf32r(v.x); v.y = tf32r(v.y); v.z = tf32r(v.z); v.w = tf32r(v.w);
        reinterpret_cast<float4*>(g_W)[i] = v;
    }
}

// ---------------- kernel 4: hand-rolled tf32 HMMA GEMM, CTA 128x256 ----------------
// smem per stage: A [ks][m][8] (2048 f), B [ks][n][8] (4096 f).
__global__ __launch_bounds__(512, 1) void gemm_kernel(float* __restrict__ out) {
    extern __shared__ float sm[];
    const int tid  = threadIdx.x;
    const int wid  = tid >> 5;
    const int lane = tid & 31;
    const int g    = lane >> 2;
    const int tig  = lane & 3;
    const int wm   = wid >> 2;     // 0..3  -> 32-row band
    const int wn   = wid & 3;      // 0..3  -> 64-col band
    const int bm0  = blockIdx.y * BM;
    const int bn0  = blockIdx.x * BN;

    float acc[2][8][4];
    #pragma unroll
    for (int a = 0; a < 2; a++)
        #pragma unroll
        for (int b = 0; b < 8; b++)
            #pragma unroll
            for (int c = 0; c < 4; c++) acc[a][b][c] = 0.f;

    auto load_stage = [&](int kt, int s) {
        float* base = sm + s * STAGE_F;
        // chunk 0: A (512 chunks of 16B)
        {
            int c  = tid;                 // 0..511
            int ks = c >> 8, w = c & 255;
            int m  = w >> 1, h = c & 1;
            cp16(base + c * 4,
                 g_X + (size_t)(bm0 + m) * KDIM + kt * BK + ks * 8 + h * 4);
        }
        // chunks 1,2: B (1024 chunks)
        #pragma unroll
        for (int t = 0; t < 2; t++) {
            int cc = t * 512 + tid;       // 0..1023
            int ks = cc >> 9, w = cc & 511;
            int n  = w >> 1, h = cc & 1;
            cp16(base + A_ST_F + cc * 4,
                 g_W + (size_t)(bn0 + n) * KDIM + kt * BK + ks * 8 + h * 4);
        }
        asm volatile("cp.async.commit_group;" ::: "memory");
    };

    load_stage(0, 0);
    load_stage(1, 1);
    load_stage(2, 2);

    for (int t = 0; t < KT; ++t) {
        if (t < KT - 2)       asm volatile("cp.async.wait_group 2;" ::: "memory");
        else if (t == KT - 2) asm volatile("cp.async.wait_group 1;" ::: "memory");
        else                  asm volatile("cp.async.wait_group 0;" ::: "memory");
        __syncthreads();

        if (t + 3 < KT) load_stage(t + 3, (t + 3) & 3);

        const float* As = sm + (t & 3) * STAGE_F;
        const float* Bs = As + A_ST_F;

        #pragma unroll
        for (int ks = 0; ks < 2; ++ks) {
            float2 alo[2], ahi[2], bfr[8];
            #pragma unroll
            for (int mt = 0; mt < 2; ++mt) {
                int r0 = wm * 32 + mt * 16 + g;
                alo[mt] = *reinterpret_cast<const float2*>(As + ks * 1024 + r0 * 8 + 2 * tig);
                ahi[mt] = *reinterpret_cast<const float2*>(As + ks * 1024 + (r0 + 8) * 8 + 2 * tig);
            }
            #pragma unroll
            for (int nt = 0; nt < 8; ++nt) {
                int n0 = wn * 64 + nt * 8 + g;
                bfr[nt] = *reinterpret_cast<const float2*>(Bs + ks * 2048 + n0 * 8 + 2 * tig);
            }
            #pragma unroll
            for (int mt = 0; mt < 2; ++mt)
                #pragma unroll
                for (int nt = 0; nt < 8; ++nt)
                    mma_tf32(acc[mt][nt],
                             alo[mt].x, ahi[mt].x, alo[mt].y, ahi[mt].y,
                             bfr[nt].x, bfr[nt].y);
        }
    }

    // epilogue: direct float2 stores (each 32B out-sector fully covered by a quad)
    #pragma unroll
    for (int mt = 0; mt < 2; ++mt) {
        #pragma unroll
        for (int nt = 0; nt < 8; ++nt) {
            int m0 = bm0 + wm * 32 + mt * 16 + g;
            int n  = bn0 + wn * 64 + nt * 8 + 2 * tig;
            *reinterpret_cast<float2*>(out + (size_t)m0 * OUT_F + n) =
                make_float2(acc[mt][nt][0], acc[mt][nt][1]);
            *reinterpret_cast<float2*>(out + (size_t)(m0 + 8) * OUT_F + n) =
                make_float2(acc[mt][nt][2], acc[mt][nt][3]);
        }
    }
}

extern "C" void kernel_launch(void* const* d_in, const int* in_sizes, int n_in,
                              void* d_out, int out_size) {
    // Size-based binding; the two nnz-sized inputs keep metadata order:
    // ortho_vals (float32) first, ortho_indices (int32) second.
    const float* x      = nullptr;
    const int*   packed = nullptr;
    const float* scales = nullptr;
    const float* vals   = nullptr;
    const int*   idxs   = nullptr;
    const int*   ptr    = nullptr;
    int nnz = 0;
    for (int i = 0; i < n_in; i++) {
        int sz = in_sizes[i];
        if (sz == MROWS * IN_F)            x      = (const float*)d_in[i];
        else if (sz == OUT_F * (IN_F / 2)) packed = (const int*)d_in[i];
        else if (sz == OUT_F)              scales = (const float*)d_in[i];
        else if (sz == OUT_F + 1)          ptr    = (const int*)d_in[i];
        else {
            nnz = sz;
            if (!vals) vals = (const float*)d_in[i];
            else       idxs = (const int*)d_in[i];
        }
    }
    float* out = (float*)d_out;

    int nx8 = (MROWS * IN_F) / 8;
    permute_x_kernel<<<(nx8 + 255) / 256, 256>>>((const float4*)x, nx8);

    int nw8 = (OUT_F * IN_F) / 8;
    dequant_kernel<<<(nw8 + 255) / 256, 256>>>((const int4*)packed, scales, nw8);

    scatter_kernel<<<OUT_F, 128>>>(vals, idxs, ptr, nnz);

    int nw4 = (OUT_F * IN_F) / 4;
    round_w_kernel<<<(nw4 + 255) / 256, 256>>>(nw4);

    cudaFuncSetAttribute(gemm_kernel, cudaFuncAttributeMaxDynamicSharedMemorySize, SMEM_BYTES);
    dim3 grid(OUT_F / BN, MROWS / BM);
    gemm_kernel<<<grid, 512, SMEM_BYTES>>>(out);
}

// round 16
// speedup vs baseline: 5.0580x; 2.0834x over previous
#include <cuda_runtime.h>
#include <cuda_fp16.h>
#include <cstdint>

#define IN_F  4096
#define OUT_F 4096
#define MROWS 4096
#define KDIM  4096

#define BM 128
#define BN 256
#define BK 16
#define STAGES 4
#define KT (KDIM / BK)              // 256
#define A_ST_B (BM * BK * 2)        // 4096 B / stage
#define B_ST_B (BN * BK * 2)        // 8192 B / stage
#define STAGE_B (A_ST_B + B_ST_B)   // 12288
#define SMEM_BYTES (STAGES * STAGE_B)   // 49152

// Scratch (allocation-free rule: device globals). fp16, K-pair-permuted within
// each k16 group: halves stored as [k0,k1,k8,k9, k2,k3,k10,k11, k4,k5,k12,k13,
// k6,k7,k14,k15] so an LDS.64 at tig*8 yields the m16n8k16 fragment pairs.
__device__ __half g_X[(size_t)MROWS * IN_F];
__device__ __half g_W[(size_t)OUT_F * IN_F];

__device__ __forceinline__ uint32_t h2u(__half2 h) {
    uint32_t u;
    *reinterpret_cast<__half2*>(&u) = h;
    return u;
}

__device__ __forceinline__ void cp16(void* dst, const void* src) {
    unsigned sd = (unsigned)__cvta_generic_to_shared(dst);
    asm volatile("cp.async.cg.shared.global [%0], [%1], 16;" :: "r"(sd), "l"(src));
}
__device__ __forceinline__ void mma_fp16(float c[4], uint32_t a0, uint32_t a1,
                                         uint32_t a2, uint32_t a3,
                                         uint32_t b0, uint32_t b1) {
    asm volatile(
        "mma.sync.aligned.m16n8k16.row.col.f32.f16.f16.f32 "
        "{%0,%1,%2,%3}, {%4,%5,%6,%7}, {%8,%9}, {%0,%1,%2,%3};"
        : "+f"(c[0]), "+f"(c[1]), "+f"(c[2]), "+f"(c[3])
        : "r"(a0), "r"(a1), "r"(a2), "r"(a3), "r"(b0), "r"(b1));
}

// ---------------- kernel 0: x -> fp16, pair-permuted k16 groups ----------------
__global__ void permute_x_kernel(const float4* __restrict__ x4, int ng) {
    int i = blockIdx.x * blockDim.x + threadIdx.x;   // k16 group index
    if (i < ng) {
        float4 f0 = x4[4 * i + 0], f1 = x4[4 * i + 1];
        float4 f2 = x4[4 * i + 2], f3 = x4[4 * i + 3];
        const float f[16] = {f0.x,f0.y,f0.z,f0.w, f1.x,f1.y,f1.z,f1.w,
                             f2.x,f2.y,f2.z,f2.w, f3.x,f3.y,f3.z,f3.w};
        uint32_t u[8];
        #pragma unroll
        for (int t = 0; t < 4; t++) {
            u[2*t]   = h2u(__floats2half2_rn(f[2*t],     f[2*t + 1]));
            u[2*t+1] = h2u(__floats2half2_rn(f[2*t + 8], f[2*t + 9]));
        }
        uint4* dst = reinterpret_cast<uint4*>(g_X) + 2 * i;
        dst[0] = make_uint4(u[0], u[1], u[2], u[3]);
        dst[1] = make_uint4(u[4], u[5], u[6], u[7]);
    }
}

// ---------------- kernel 1: dequant int4 -> fp16 (q-8)*s, pair-permuted ----------------
__global__ void dequant_kernel(const int4* __restrict__ packed4,
                               const float* __restrict__ scales, int ng) {
    int i = blockIdx.x * blockDim.x + threadIdx.x;   // k16 group (8 packed words)
    if (i < ng) {
        int4 pa = packed4[2 * i], pb = packed4[2 * i + 1];
        const int w[8] = {pa.x, pa.y, pa.z, pa.w, pb.x, pb.y, pb.z, pb.w};
        float s = scales[i >> 8];                     // 256 groups per row
        uint32_t u[8];
        #pragma unroll
        for (int t = 0; t < 4; t++) {
            float e0 = (float)((w[t] & 15) - 8) * s;
            float e1 = (float)(((w[t] >> 4) & 15) - 8) * s;
            float e2 = (float)((w[t + 4] & 15) - 8) * s;
            float e3 = (float)(((w[t + 4] >> 4) & 15) - 8) * s;
            u[2*t]   = h2u(__floats2half2_rn(e0, e1));
            u[2*t+1] = h2u(__floats2half2_rn(e2, e3));
        }
        uint4* dst = reinterpret_cast<uint4*>(g_W) + 2 * i;
        dst[0] = make_uint4(u[0], u[1], u[2], u[3]);
        dst[1] = make_uint4(u[4], u[5], u[6], u[7]);
    }
}

// ---------------- kernel 2: CSR scatter-add residual (fp16 atomics, permuted col) ----
__global__ void scatter_kernel(const float* __restrict__ vals,
                               const int* __restrict__ idxs,
                               const int* __restrict__ ptr,
                               int nnz) {
    int r = blockIdx.x;
    int s = ptr[r], e = ptr[r + 1];
    if (e > nnz) e = nnz;
    if (s > nnz) s = nnz;
    if (s < 0) s = 0;
    for (int j = s + threadIdx.x; j < e; j += blockDim.x) {
        int c = idxs[j];
        if ((unsigned)c < (unsigned)IN_F) {
            int kk = c & 15;
            int slot = ((kk >> 1) & 3) * 4 + (kk & 1) + ((kk >> 3) << 1);
            int pc = (c & ~15) + slot;
            atomicAdd(&g_W[(size_t)r * IN_F + pc], __float2half(vals[j]));
        }
    }
}

// ---------------- kernel 3: fp16 HMMA GEMM, CTA 128x256, warp 32x64 ----------------
__global__ __launch_bounds__(512, 1) void gemm_kernel(float* __restrict__ out) {
    extern __shared__ char smem[];
    const int tid  = threadIdx.x;
    const int wid  = tid >> 5;
    const int lane = tid & 31;
    const int g    = lane >> 2;
    const int tig  = lane & 3;
    const int wm   = wid >> 2;
    const int wn   = wid & 3;
    const int bm0  = blockIdx.y * BM;
    const int bn0  = blockIdx.x * BN;

    float acc[2][8][4];
    #pragma unroll
    for (int a = 0; a < 2; a++)
        #pragma unroll
        for (int b = 0; b < 8; b++)
            #pragma unroll
            for (int c = 0; c < 4; c++) acc[a][b][c] = 0.f;

    auto load_stage = [&](int kt, int s) {
        char* base = smem + s * STAGE_B;
        #pragma unroll
        for (int t = 0; t < 2; t++) {
            int c = t * 512 + tid;             // 0..1023; 768 used
            if (c < 256) {                     // A: 256 x 16B
                int m = c >> 1, h = c & 1;
                cp16(base + m * 32 + h * 16,
                     g_X + (size_t)(bm0 + m) * KDIM + kt * BK + h * 8);
            } else if (c < 768) {              // B: 512 x 16B
                int cc = c - 256;
                int n = cc >> 1, h = cc & 1;
                cp16(base + A_ST_B + n * 32 + h * 16,
                     g_W + (size_t)(bn0 + n) * KDIM + kt * BK + h * 8);
            }
        }
        asm volatile("cp.async.commit_group;" ::: "memory");
    };

    load_stage(0, 0);
    load_stage(1, 1);
    load_stage(2, 2);

    for (int t = 0; t < KT; ++t) {
        if (t < KT - 2)       asm volatile("cp.async.wait_group 2;" ::: "memory");
        else if (t == KT - 2) asm volatile("cp.async.wait_group 1;" ::: "memory");
        else                  asm volatile("cp.async.wait_group 0;" ::: "memory");
        __syncthreads();

        if (t + 3 < KT) load_stage(t + 3, (t + 3) & 3);

        const char* As = smem + (t & 3) * STAGE_B;
        const char* Bs = As + A_ST_B;

        uint2 afr[2][2];
        #pragma unroll
        for (int mt = 0; mt < 2; ++mt) {
            int r0 = wm * 32 + mt * 16 + g;
            afr[mt][0] = *reinterpret_cast<const uint2*>(As + r0 * 32 + tig * 8);
            afr[mt][1] = *reinterpret_cast<const uint2*>(As + (r0 + 8) * 32 + tig * 8);
        }
        uint2 bfr[8];
        #pragma unroll
        for (int nt = 0; nt < 8; ++nt) {
            int n0 = wn * 64 + nt * 8 + g;
            bfr[nt] = *reinterpret_cast<const uint2*>(Bs + n0 * 32 + tig * 8);
        }
        #pragma unroll
        for (int mt = 0; mt < 2; ++mt)
            #pragma unroll
            for (int nt = 0; nt < 8; ++nt)
                mma_fp16(acc[mt][nt],
                         afr[mt][0].x, afr[mt][1].x, afr[mt][0].y, afr[mt][1].y,
                         bfr[nt].x, bfr[nt].y);
    }

    // epilogue: direct float2 stores
    #pragma unroll
    for (int mt = 0; mt < 2; ++mt) {
        #pragma unroll
        for (int nt = 0; nt < 8; ++nt) {
            int m0 = bm0 + wm * 32 + mt * 16 + g;
            int n  = bn0 + wn * 64 + nt * 8 + 2 * tig;
            *reinterpret_cast<float2*>(out + (size_t)m0 * OUT_F + n) =
                make_float2(acc[mt][nt][0], acc[mt][nt][1]);
            *reinterpret_cast<float2*>(out + (size_t)(m0 + 8) * OUT_F + n) =
                make_float2(acc[mt][nt][2], acc[mt][nt][3]);
        }
    }
}

extern "C" void kernel_launch(void* const* d_in, const int* in_sizes, int n_in,
                              void* d_out, int out_size) {
    // Size-based binding; the two nnz-sized inputs keep metadata order:
    // ortho_vals (float32) first, ortho_indices (int32) second.
    const float* x      = nullptr;
    const int*   packed = nullptr;
    const float* scales = nullptr;
    const float* vals   = nullptr;
    const int*   idxs   = nullptr;
    const int*   ptr    = nullptr;
    int nnz = 0;
    for (int i = 0; i < n_in; i++) {
        int sz = in_sizes[i];
        if (sz == MROWS * IN_F)            x      = (const float*)d_in[i];
        else if (sz == OUT_F * (IN_F / 2)) packed = (const int*)d_in[i];
        else if (sz == OUT_F)              scales = (const float*)d_in[i];
        else if (sz == OUT_F + 1)          ptr    = (const int*)d_in[i];
        else {
            nnz = sz;
            if (!vals) vals = (const float*)d_in[i];
            else       idxs = (const int*)d_in[i];
        }
    }
    float* out = (float*)d_out;

    int ngx = (MROWS * IN_F) / 16;
    permute_x_kernel<<<(ngx + 255) / 256, 256>>>((const float4*)x, ngx);

    int ngw = (OUT_F * IN_F) / 16;
    dequant_kernel<<<(ngw + 255) / 256, 256>>>((const int4*)packed, scales, ngw);

    scatter_kernel<<<OUT_F, 128>>>(vals, idxs, ptr, nnz);

    cudaFuncSetAttribute(gemm_kernel, cudaFuncAttributeMaxDynamicSharedMemorySize, SMEM_BYTES);
    dim3 grid(OUT_F / BN, MROWS / BM);
    gemm_kernel<<<grid, 512, SMEM_BYTES>>>(out);
}